// round 6
// baseline (speedup 1.0000x reference)
#include <cuda_runtime.h>
#include <cuda_bf16.h>
#include <math.h>
#include <stdint.h>

// Problem constants
#define N_ROWS 256
#define N_EMB  16384
#define DIMK   2048
#define KNN_   6
#define N_NEI  (N_ROWS * KNN_)   // 1536
#define INV_BETA 20.0f
#define DELTA   2.0e-3f
#define UCAP    (1 << 20)

// ---------------- scratch (device globals) ----------------
__device__ float         g_L[(size_t)N_ROWS * N_EMB];     // 16 MB logits
__device__ __nv_bfloat16 g_em_hi[(size_t)N_EMB * DIMK];
__device__ __nv_bfloat16 g_em_lo[(size_t)N_EMB * DIMK];
__device__ __nv_bfloat16 g_in_hi[(size_t)N_ROWS * DIMK];
__device__ __nv_bfloat16 g_in_lo[(size_t)N_ROWS * DIMK];
__device__ int   g_tidx[N_NEI];
__device__ float g_tval[N_NEI];
__device__ float g_lse[N_ROWS];
__device__ float g_tlog[N_ROWS];
__device__ float g_thr[N_NEI];
__device__ int   g_anc[N_NEI];
__device__ int   g_cnt[N_NEI];
__device__ int   g_tgt[N_ROWS];
__device__ unsigned g_ucnt;
__device__ int2  g_upair[UCAP];

// ---------------- helpers ----------------
__device__ __forceinline__ uint32_t smem_u32(const void* p) {
    uint32_t a;
    asm("{ .reg .u64 t; cvta.to.shared.u64 t, %1; cvt.u32.u64 %0, t; }" : "=r"(a) : "l"(p));
    return a;
}
__device__ __forceinline__ void cp16(uint32_t dst, const void* src) {
    asm volatile("cp.async.cg.shared.global [%0], [%1], 16;" :: "r"(dst), "l"(src));
}
#define CP_COMMIT() asm volatile("cp.async.commit_group;" ::: "memory")
#define CP_WAIT1()  asm volatile("cp.async.wait_group 1;" ::: "memory")

__device__ __forceinline__ void ldsm4(uint32_t* r, uint32_t addr) {
    asm volatile("ldmatrix.sync.aligned.m8n8.x4.shared.b16 {%0,%1,%2,%3}, [%4];"
                 : "=r"(r[0]), "=r"(r[1]), "=r"(r[2]), "=r"(r[3]) : "r"(addr));
}
__device__ __forceinline__ void mma16816(float* d, const uint32_t* a, const uint32_t* b) {
    asm volatile(
        "mma.sync.aligned.m16n8k16.row.col.f32.bf16.bf16.f32 "
        "{%0,%1,%2,%3}, {%4,%5,%6,%7}, {%8,%9}, {%0,%1,%2,%3};"
        : "+f"(d[0]), "+f"(d[1]), "+f"(d[2]), "+f"(d[3])
        : "r"(a[0]), "r"(a[1]), "r"(a[2]), "r"(a[3]), "r"(b[0]), "r"(b[1]));
}

// ---------------- targets dtype normalization ----------------
__global__ void load_targets_kernel(const int* __restrict__ t32)
{
    __shared__ int is64;
    if (threadIdx.x == 0) {
        int z = 1;
        #pragma unroll
        for (int i = 1; i < 64; i += 2)
            if (t32[i] != 0) z = 0;
        is64 = z;
    }
    __syncthreads();
    int m = threadIdx.x;
    g_tgt[m] = is64 ? t32[2 * m] : t32[m];
}

// ---------------- fp32 -> bf16 hi/lo split ----------------
template<int WHICH>   // 0 = em, 1 = inputs
__global__ void cvt_kernel(const float* __restrict__ src, int n4)
{
    int i = blockIdx.x * blockDim.x + threadIdx.x;
    if (i >= n4) return;
    __nv_bfloat16* hi = WHICH ? g_in_hi : g_em_hi;
    __nv_bfloat16* lo = WHICH ? g_in_lo : g_em_lo;
    float4 v = ((const float4*)src)[i];
    __nv_bfloat162 h0, h1, l0, l1;
    h0.x = __float2bfloat16_rn(v.x);  h0.y = __float2bfloat16_rn(v.y);
    h1.x = __float2bfloat16_rn(v.z);  h1.y = __float2bfloat16_rn(v.w);
    l0.x = __float2bfloat16_rn(v.x - __bfloat162float(h0.x));
    l0.y = __float2bfloat16_rn(v.y - __bfloat162float(h0.y));
    l1.x = __float2bfloat16_rn(v.z - __bfloat162float(h1.x));
    l1.y = __float2bfloat16_rn(v.w - __bfloat162float(h1.y));
    ((__nv_bfloat162*)hi)[2 * i]     = h0;
    ((__nv_bfloat162*)hi)[2 * i + 1] = h1;
    ((__nv_bfloat162*)lo)[2 * i]     = l0;
    ((__nv_bfloat162*)lo)[2 * i + 1] = l1;
}

// ---------------- HMMA GEMM: 128x128 tiles, BK=32, 8 warps (2x4) ----------------
#define PITCH 40                       // padded row length (elems) -> conflict-free ldmatrix
#define PART  (128 * PITCH * 2)        // 10240 B per matrix part
#define KIT   (DIMK / 32)              // 64 k-iterations

template<bool SPLIT, bool GATHER, bool COUNT>
__global__ __launch_bounds__(256)
void mma_gemm(float scale)
{
    extern __shared__ char dsm[];
    const uint32_t sb = smem_u32(dsm);
    constexpr int A_HI = 0;
    constexpr int A_LO = PART;                       // SPLIT only
    constexpr int B_HI = SPLIT ? 2 * PART : PART;
    constexpr int B_LO = 3 * PART;                   // SPLIT only
    constexpr int STAGE = (SPLIT ? 4 : 2) * PART;

    const int t    = threadIdx.x;
    const int wid  = t >> 5, lane = t & 31;
    const int wm   = wid >> 2;          // 0..1  (64-row half)
    const int wn   = wid & 3;           // 0..3  (32-col quarter)
    const int bm   = blockIdx.y * 128;
    const int bn   = blockIdx.x * 128;

    __shared__ float sthr[128];
    __shared__ int   sanc[128];
    __shared__ int   scnt[128];
    if (COUNT && t < 128) {
        sthr[t] = g_thr[bm + t];
        sanc[t] = g_anc[bm + t];
        scnt[t] = 0;
    }

    // per-thread global row pointers for cp.async (row = t/2, half = t&1)
    const int lr   = t >> 1;
    const int half = (t & 1) * 16;
    int arow = bm + lr;
    if (GATHER) arow = g_tidx[arow];
    const __nv_bfloat16* gah = (GATHER ? g_em_hi : g_in_hi) + (size_t)arow * DIMK + half;
    const __nv_bfloat16* gal = SPLIT ? ((GATHER ? g_em_lo : g_in_lo) + (size_t)arow * DIMK + half) : nullptr;
    const __nv_bfloat16* gbh = g_em_hi + (size_t)(bn + lr) * DIMK + half;
    const __nv_bfloat16* gbl = SPLIT ? (g_em_lo + (size_t)(bn + lr) * DIMK + half) : nullptr;

    const uint32_t drow = sb + (uint32_t)(lr * PITCH + half) * 2;

    auto load_stage = [&](int s, int k0) {
        uint32_t d = drow + s * STAGE;
        cp16(d + A_HI,      gah + k0);
        cp16(d + A_HI + 16, gah + k0 + 8);
        cp16(d + B_HI,      gbh + k0);
        cp16(d + B_HI + 16, gbh + k0 + 8);
        if (SPLIT) {
            cp16(d + A_LO,      gal + k0);
            cp16(d + A_LO + 16, gal + k0 + 8);
            cp16(d + B_LO,      gbl + k0);
            cp16(d + B_LO + 16, gbl + k0 + 8);
        }
    };

    float acc[4][4][4];
    #pragma unroll
    for (int i = 0; i < 4; i++)
        #pragma unroll
        for (int j = 0; j < 4; j++)
            #pragma unroll
            for (int e = 0; e < 4; e++) acc[i][j][e] = 0.f;

    load_stage(0, 0);  CP_COMMIT();
    load_stage(1, 32); CP_COMMIT();

    // ldmatrix address components: row-in-16 = lane%16, col8 = (lane/16)*8
    const int lrow16 = lane & 15;
    const int lcol8  = (lane >> 4) * 8;

    for (int it = 0; it < KIT; it++) {
        const int s = it & 1;
        CP_WAIT1();
        __syncthreads();

        const uint32_t base = sb + s * STAGE;
        #pragma unroll
        for (int kk = 0; kk < 2; kk++) {
            const int colb = kk * 16 + lcol8;
            uint32_t ah[4][4], bh[4][2];
            #pragma unroll
            for (int i = 0; i < 4; i++) {
                uint32_t ad = base + A_HI +
                    (uint32_t)((wm * 64 + i * 16 + lrow16) * PITCH + colb) * 2;
                ldsm4(ah[i], ad);
            }
            #pragma unroll
            for (int jj = 0; jj < 2; jj++) {
                uint32_t r[4];
                uint32_t bd = base + B_HI +
                    (uint32_t)((wn * 32 + jj * 16 + lrow16) * PITCH + colb) * 2;
                ldsm4(r, bd);
                bh[jj * 2][0]     = r[0]; bh[jj * 2][1]     = r[2];
                bh[jj * 2 + 1][0] = r[1]; bh[jj * 2 + 1][1] = r[3];
            }
            #pragma unroll
            for (int i = 0; i < 4; i++)
                #pragma unroll
                for (int j = 0; j < 4; j++)
                    mma16816(acc[i][j], ah[i], bh[j]);

            if (SPLIT) {
                uint32_t al[4][4], bl[4][2];
                #pragma unroll
                for (int i = 0; i < 4; i++) {
                    uint32_t ad = base + A_LO +
                        (uint32_t)((wm * 64 + i * 16 + lrow16) * PITCH + colb) * 2;
                    ldsm4(al[i], ad);
                }
                #pragma unroll
                for (int jj = 0; jj < 2; jj++) {
                    uint32_t r[4];
                    uint32_t bd = base + B_LO +
                        (uint32_t)((wn * 32 + jj * 16 + lrow16) * PITCH + colb) * 2;
                    ldsm4(r, bd);
                    bl[jj * 2][0]     = r[0]; bl[jj * 2][1]     = r[2];
                    bl[jj * 2 + 1][0] = r[1]; bl[jj * 2 + 1][1] = r[3];
                }
                #pragma unroll
                for (int i = 0; i < 4; i++)
                    #pragma unroll
                    for (int j = 0; j < 4; j++) {
                        mma16816(acc[i][j], ah[i], bl[j]);
                        mma16816(acc[i][j], al[i], bh[j]);
                    }
            }
        }
        __syncthreads();
        if (it + 2 < KIT) load_stage(s, (it + 2) * 32);
        CP_COMMIT();
    }

    // ---------------- epilogue ----------------
    const int rr = lane >> 2;            // 0..7
    const int c2 = (lane & 3) * 2;
    if (!COUNT) {
        #pragma unroll
        for (int i = 0; i < 4; i++) {
            const int m0 = bm + wm * 64 + i * 16 + rr;
            const int m1 = m0 + 8;
            #pragma unroll
            for (int j = 0; j < 4; j++) {
                const int n0 = bn + wn * 32 + j * 8 + c2;
                float2 v0 = make_float2(acc[i][j][0] * scale, acc[i][j][1] * scale);
                float2 v1 = make_float2(acc[i][j][2] * scale, acc[i][j][3] * scale);
                *(float2*)&g_L[(size_t)m0 * N_EMB + n0] = v0;
                *(float2*)&g_L[(size_t)m1 * N_EMB + n0] = v1;
            }
        }
    } else {
        #pragma unroll
        for (int i = 0; i < 4; i++) {
            const int lm0 = wm * 64 + i * 16 + rr;
            const int lm1 = lm0 + 8;
            const float t0 = sthr[lm0], t1 = sthr[lm1];
            const int   a0 = sanc[lm0], a1 = sanc[lm1];
            int c0 = 0, c1 = 0;
            #pragma unroll
            for (int j = 0; j < 4; j++) {
                const int n0 = bn + wn * 32 + j * 8 + c2;
                #pragma unroll
                for (int e = 0; e < 2; e++) {
                    const int col = n0 + e;
                    {   // row lm0
                        float s = acc[i][j][e];
                        if (col != a0) {
                            if (s > t0 + DELTA) c0++;
                            else if (s > t0 - DELTA) {
                                unsigned idx = atomicAdd(&g_ucnt, 1u);
                                if (idx < UCAP) g_upair[idx] = make_int2(bm + lm0, col);
                            }
                        }
                    }
                    {   // row lm1
                        float s = acc[i][j][2 + e];
                        if (col != a1) {
                            if (s > t1 + DELTA) c1++;
                            else if (s > t1 - DELTA) {
                                unsigned idx = atomicAdd(&g_ucnt, 1u);
                                if (idx < UCAP) g_upair[idx] = make_int2(bm + lm1, col);
                            }
                        }
                    }
                }
            }
            if (c0) atomicAdd(&scnt[lm0], c0);
            if (c1) atomicAdd(&scnt[lm1], c1);
        }
        __syncthreads();
        if (t < 128 && scnt[t]) atomicAdd(&g_cnt[bm + t], scnt[t]);
    }
}

// ---------------- exact fp32 fixup for borderline sims ----------------
__global__ __launch_bounds__(256)
void fixup_kernel(const float* __restrict__ em)
{
    __shared__ float red[256];
    const unsigned n = min(g_ucnt, (unsigned)UCAP);
    for (unsigned p = blockIdx.x; p < n; p += gridDim.x) {
        const int2 pr = g_upair[p];
        const int r = pr.x, c = pr.y;
        const float* x = em + (size_t)g_tidx[r] * DIMK;
        const float* y = em + (size_t)c * DIMK;
        float s = 0.f;
        for (int j = threadIdx.x * 4; j < DIMK; j += 256 * 4) {
            float4 xv = *(const float4*)(x + j);
            float4 yv = *(const float4*)(y + j);
            s += xv.x * yv.x + xv.y * yv.y + xv.z * yv.z + xv.w * yv.w;
        }
        red[threadIdx.x] = s;
        __syncthreads();
        for (int sft = 128; sft > 0; sft >>= 1) {
            if (threadIdx.x < sft) red[threadIdx.x] += red[threadIdx.x + sft];
            __syncthreads();
        }
        if (threadIdx.x == 0) {
            float tv = g_thr[r];
            if (red[0] > tv || (red[0] == tv && c < g_anc[r])) atomicAdd(&g_cnt[r], 1);
        }
        __syncthreads();
    }
}

// ---------------- per-row: top-6 + logsumexp + target logit ----------------
__global__ __launch_bounds__(256)
void row_reduce_kernel()
{
    const int m   = blockIdx.x;
    const int tid = threadIdx.x;
    const float* row = g_L + (size_t)m * N_EMB;

    float bv[KNN_]; int bi[KNN_];
    #pragma unroll
    for (int k = 0; k < KNN_; k++) { bv[k] = -3.0e38f; bi[k] = 0x7fffffff; }
    float worst = -3.0e38f;
    float mx = -3.0e38f, sum = 0.f;

    for (int j = tid; j < N_EMB; j += 256) {
        float v = row[j];
        if (v > mx) { sum = sum * __expf(mx - v) + 1.f; mx = v; }
        else        { sum += __expf(v - mx); }
        if (v > worst) {
            int p = KNN_ - 1;
            while (p > 0 && (v > bv[p - 1])) { bv[p] = bv[p - 1]; bi[p] = bi[p - 1]; p--; }
            bv[p] = v; bi[p] = j;
            worst = bv[KNN_ - 1];
        }
    }

    __shared__ float sv[256 * KNN_];
    __shared__ int   si[256 * KNN_];
    __shared__ float rv[256];
    __shared__ int   ri[256];
    __shared__ int   rt[256];
    __shared__ float smx[256];
    __shared__ float ssum[256];

    #pragma unroll
    for (int k = 0; k < KNN_; k++) { sv[tid * KNN_ + k] = bv[k]; si[tid * KNN_ + k] = bi[k]; }
    smx[tid] = mx; ssum[tid] = sum;
    __syncthreads();

    for (int s = 128; s > 0; s >>= 1) {
        if (tid < s) {
            float m1 = smx[tid], m2 = smx[tid + s];
            float M  = fmaxf(m1, m2);
            ssum[tid] = ssum[tid] * __expf(m1 - M) + ssum[tid + s] * __expf(m2 - M);
            smx[tid]  = M;
        }
        __syncthreads();
    }
    if (tid == 0) {
        g_lse[m]  = smx[0] + logf(ssum[0]);
        g_tlog[m] = row[g_tgt[m]];
    }

    int head = 0;
    for (int round = 0; round < KNN_; round++) {
        float mv; int mi;
        if (head < KNN_) { mv = sv[tid * KNN_ + head]; mi = si[tid * KNN_ + head]; }
        else             { mv = -3.0e38f; mi = 0x7fffffff; }
        rv[tid] = mv; ri[tid] = mi; rt[tid] = tid;
        __syncthreads();
        for (int s = 128; s > 0; s >>= 1) {
            if (tid < s) {
                float v2 = rv[tid + s]; int i2 = ri[tid + s];
                if (v2 > rv[tid] || (v2 == rv[tid] && i2 < ri[tid])) {
                    rv[tid] = v2; ri[tid] = i2; rt[tid] = rt[tid + s];
                }
            }
            __syncthreads();
        }
        if (tid == 0) { g_tval[m * KNN_ + round] = rv[0]; g_tidx[m * KNN_ + round] = ri[0]; }
        int w = rt[0];
        __syncthreads();
        if (tid == w) head++;
    }
}

// ---------------- thresholds (+ zero counters/uncertain list) ----------------
__global__ __launch_bounds__(256)
void thr_kernel(const float* __restrict__ em)
{
    const int r = blockIdx.x;
    const int m = r / KNN_;
    const int t = g_tidx[r];
    const int a = g_tidx[m * KNN_];
    if (r == 0 && threadIdx.x == 0) g_ucnt = 0;
    const float* x = em + (size_t)t * DIMK;
    const float* y = em + (size_t)a * DIMK;
    float s = 0.f;
    for (int j = threadIdx.x * 4; j < DIMK; j += 256 * 4) {
        float4 xv = *(const float4*)(x + j);
        float4 yv = *(const float4*)(y + j);
        s += xv.x * yv.x + xv.y * yv.y + xv.z * yv.z + xv.w * yv.w;
    }
    __shared__ float red[256];
    red[threadIdx.x] = s;
    __syncthreads();
    for (int sft = 128; sft > 0; sft >>= 1) {
        if (threadIdx.x < sft) red[threadIdx.x] += red[threadIdx.x + sft];
        __syncthreads();
    }
    if (threadIdx.x == 0) { g_thr[r] = red[0]; g_anc[r] = a; g_cnt[r] = 0; }
}

// ---------------- final losses ----------------
__global__ __launch_bounds__(256)
void finalize_kernel(float* __restrict__ out)
{
    const int m = threadIdx.x;
    float l  = g_lse[m];
    float lt = g_tlog[m];
    int  tgt = g_tgt[m];
    float p_t = expf(lt - l);
    float P_rec = 0.f, extra = 0.f;
    #pragma unroll
    for (int k = 0; k < KNN_; k++) {
        int idx = g_tidx[m * KNN_ + k];
        if (idx != tgt && g_cnt[m * KNN_ + k] <= 5) {
            float v = g_tval[m * KNN_ + k];
            P_rec += expf(v - l);
            extra += 0.5f * (v - l);
        }
    }
    float beta = -((lt - l) + extra);
    const float LOG_HALF = -0.6931471805599453f;
    const float LOG_EPS  = -9.210340371976182f;
    float alpha = -(P_rec * LOG_HALF + (1.f - p_t - P_rec) * LOG_EPS);

    __shared__ float sa[256], sb2[256];
    sa[m] = alpha; sb2[m] = beta;
    __syncthreads();
    for (int s = 128; s > 0; s >>= 1) {
        if (m < s) { sa[m] += sa[m + s]; sb2[m] += sb2[m + s]; }
        __syncthreads();
    }
    if (m == 0) {
        out[0] = 0.05f * (sa[0] / 256.f);
        out[1] = sb2[0] / 256.f;
    }
}

// ---------------- launch ----------------
extern "C" void kernel_launch(void* const* d_in, const int* in_sizes, int n_in,
                              void* d_out, int out_size)
{
    const float* inputs  = (const float*)d_in[0];
    const float* em      = (const float*)d_in[1];
    const int*   targets = (const int*)d_in[2];
    float* out = (float*)d_out;
    (void)in_sizes; (void)n_in; (void)out_size;

    const int smem_split  = 2 * 4 * PART;   // 81920
    const int smem_single = 2 * 2 * PART;   // 40960
    cudaFuncSetAttribute(mma_gemm<true,  false, false>,
                         cudaFuncAttributeMaxDynamicSharedMemorySize, smem_split);
    cudaFuncSetAttribute(mma_gemm<false, true,  true>,
                         cudaFuncAttributeMaxDynamicSharedMemorySize, smem_single);

    load_targets_kernel<<<1, 256>>>(targets);
    cvt_kernel<0><<<(N_EMB * DIMK / 4) / 256, 256>>>(em, N_EMB * DIMK / 4);
    cvt_kernel<1><<<(N_ROWS * DIMK / 4) / 256, 256>>>(inputs, N_ROWS * DIMK / 4);

    // logits = inputs @ em.T * 20  (split-3 bf16 HMMA)
    mma_gemm<true, false, false>
        <<<dim3(N_EMB / 128, N_ROWS / 128), 256, smem_split>>>(INV_BETA);
    row_reduce_kernel<<<N_ROWS, 256>>>();
    thr_kernel<<<N_NEI, 256>>>(em);
    // sims GEMM (single bf16) + fused count + borderline capture
    mma_gemm<false, true, true>
        <<<dim3(N_EMB / 128, N_NEI / 128), 256, smem_single>>>(1.0f);
    fixup_kernel<<<512, 256>>>(em);
    finalize_kernel<<<1, 256>>>(out);
}

// round 7
// speedup vs baseline: 4.3886x; 4.3886x over previous
#include <cuda_runtime.h>
#include <cuda_fp16.h>
#include <math.h>
#include <stdint.h>

// Problem constants
#define N_ROWS 256
#define N_EMB  16384
#define DIMK   2048
#define KNN_   6
#define N_NEI  (N_ROWS * KNN_)   // 1536
#define INV_BETA 20.0f
#define DELTA   5.0e-5f
#define UCAP    (1 << 20)

// ---------------- scratch (device globals) ----------------
__device__ float  g_L[(size_t)N_ROWS * N_EMB];     // 16 MB logits
__device__ __half g_em_h[(size_t)N_EMB * DIMK];    // 64 MB
__device__ __half g_in_h[(size_t)N_ROWS * DIMK];   // 1 MB
__device__ int   g_tidx[N_NEI];
__device__ float g_tval[N_NEI];
__device__ float g_lse[N_ROWS];
__device__ float g_tlog[N_ROWS];
__device__ float g_thr[N_NEI];
__device__ int   g_anc[N_NEI];
__device__ int   g_cnt[N_NEI];
__device__ int   g_tgt[N_ROWS];
__device__ unsigned g_ucnt;
__device__ int2  g_upair[UCAP];

// ---------------- helpers ----------------
__device__ __forceinline__ uint32_t smem_u32(const void* p) {
    uint32_t a;
    asm("{ .reg .u64 t; cvta.to.shared.u64 t, %1; cvt.u32.u64 %0, t; }" : "=r"(a) : "l"(p));
    return a;
}
__device__ __forceinline__ void cp16(uint32_t dst, const void* src) {
    asm volatile("cp.async.cg.shared.global [%0], [%1], 16;" :: "r"(dst), "l"(src));
}
#define CP_COMMIT() asm volatile("cp.async.commit_group;" ::: "memory")
#define CP_WAIT1()  asm volatile("cp.async.wait_group 1;" ::: "memory")

__device__ __forceinline__ void ldsm4(uint32_t* r, uint32_t addr) {
    asm volatile("ldmatrix.sync.aligned.m8n8.x4.shared.b16 {%0,%1,%2,%3}, [%4];"
                 : "=r"(r[0]), "=r"(r[1]), "=r"(r[2]), "=r"(r[3]) : "r"(addr));
}
__device__ __forceinline__ void mma16816(float* d, const uint32_t* a, const uint32_t* b) {
    asm volatile(
        "mma.sync.aligned.m16n8k16.row.col.f32.f16.f16.f32 "
        "{%0,%1,%2,%3}, {%4,%5,%6,%7}, {%8,%9}, {%0,%1,%2,%3};"
        : "+f"(d[0]), "+f"(d[1]), "+f"(d[2]), "+f"(d[3])
        : "r"(a[0]), "r"(a[1]), "r"(a[2]), "r"(a[3]), "r"(b[0]), "r"(b[1]));
}

// ---------------- targets dtype normalization ----------------
__global__ void load_targets_kernel(const int* __restrict__ t32)
{
    __shared__ int is64;
    if (threadIdx.x == 0) {
        int z = 1;
        #pragma unroll
        for (int i = 1; i < 64; i += 2)
            if (t32[i] != 0) z = 0;
        is64 = z;
    }
    __syncthreads();
    int m = threadIdx.x;
    g_tgt[m] = is64 ? t32[2 * m] : t32[m];
}

// ---------------- fp32 -> fp16 ----------------
template<int WHICH>   // 0 = em, 1 = inputs
__global__ void cvt_kernel(const float* __restrict__ src, int n4)
{
    int i = blockIdx.x * blockDim.x + threadIdx.x;
    if (i >= n4) return;
    __half* dst = WHICH ? g_in_h : g_em_h;
    float4 v = ((const float4*)src)[i];
    __half2 h0 = __floats2half2_rn(v.x, v.y);
    __half2 h1 = __floats2half2_rn(v.z, v.w);
    ((__half2*)dst)[2 * i]     = h0;
    ((__half2*)dst)[2 * i + 1] = h1;
}

// ---------------- fp16 HMMA GEMM: 256x128 tiles, BK=32, 8 warps (4x2), 3-stage ----------------
#define BLKM 256
#define BLKN 128
#define PITCH 40                       // padded row length (halves)
#define A_BYTES (BLKM * PITCH * 2)     // 20480
#define B_BYTES (BLKN * PITCH * 2)     // 10240
#define STAGE   (A_BYTES + B_BYTES)    // 30720
#define NSTAGE  3
#define GEMM_SMEM (NSTAGE * STAGE)     // 92160
#define KIT   (DIMK / 32)              // 64

template<bool GATHER, bool COUNT>
__global__ __launch_bounds__(256, 1)
void mma_gemm(float scale)
{
    extern __shared__ char dsm[];
    const uint32_t sb = smem_u32(dsm);

    const int t    = threadIdx.x;
    const int wid  = t >> 5, lane = t & 31;
    const int wm   = wid >> 1;          // 0..3  (64-row quarter)
    const int wn   = wid & 1;           // 0..1  (64-col half)
    const int bm   = blockIdx.y * BLKM;
    const int bn   = blockIdx.x * BLKN;

    __shared__ float sthr[BLKM];
    __shared__ int   sanc[BLKM];
    __shared__ int   scnt[BLKM];
    if (COUNT) {
        sthr[t] = g_thr[bm + t];
        sanc[t] = g_anc[bm + t];
        scnt[t] = 0;
    }

    // A: thread t owns row t (4 cp16). B: thread t owns row t>>1, 16-col half t&1 (2 cp16).
    int arow = bm + t;
    if (GATHER) arow = g_tidx[arow];
    const __half* ga = (GATHER ? g_em_h : g_in_h) + (size_t)arow * DIMK;
    const __half* gb = g_em_h + (size_t)(bn + (t >> 1)) * DIMK + (t & 1) * 16;

    const uint32_t da = sb + (uint32_t)(t * PITCH) * 2;
    const uint32_t db = sb + A_BYTES + (uint32_t)((t >> 1) * PITCH + (t & 1) * 16) * 2;

    auto load_stage = [&](int s, int k0) {
        uint32_t o = (uint32_t)(s * STAGE);
        #pragma unroll
        for (int q = 0; q < 4; q++)
            cp16(da + o + q * 16, ga + k0 + q * 8);
        cp16(db + o,      gb + k0);
        cp16(db + o + 16, gb + k0 + 8);
    };

    float acc[4][8][4];
    #pragma unroll
    for (int i = 0; i < 4; i++)
        #pragma unroll
        for (int j = 0; j < 8; j++)
            #pragma unroll
            for (int e = 0; e < 4; e++) acc[i][j][e] = 0.f;

    load_stage(0, 0);  CP_COMMIT();
    load_stage(1, 32); CP_COMMIT();

    const int lrow16 = lane & 15;
    const int lcol8  = (lane >> 4) * 8;

    for (int it = 0; it < KIT; it++) {
        CP_WAIT1();
        __syncthreads();
        if (it + 2 < KIT) load_stage((it + 2) % NSTAGE, (it + 2) * 32);
        CP_COMMIT();

        const uint32_t base = sb + (uint32_t)((it % NSTAGE) * STAGE);
        #pragma unroll
        for (int kk = 0; kk < 2; kk++) {
            const int colb = kk * 16 + lcol8;
            uint32_t ah[4][4], bh[8][2];
            #pragma unroll
            for (int i = 0; i < 4; i++) {
                uint32_t ad = base +
                    (uint32_t)((wm * 64 + i * 16 + lrow16) * PITCH + colb) * 2;
                ldsm4(ah[i], ad);
            }
            #pragma unroll
            for (int jj = 0; jj < 4; jj++) {
                uint32_t r[4];
                uint32_t bd = base + A_BYTES +
                    (uint32_t)((wn * 64 + jj * 16 + lrow16) * PITCH + colb) * 2;
                ldsm4(r, bd);
                bh[jj * 2][0]     = r[0]; bh[jj * 2][1]     = r[2];
                bh[jj * 2 + 1][0] = r[1]; bh[jj * 2 + 1][1] = r[3];
            }
            #pragma unroll
            for (int i = 0; i < 4; i++)
                #pragma unroll
                for (int j = 0; j < 8; j++)
                    mma16816(acc[i][j], ah[i], bh[j]);
        }
        __syncthreads();
    }

    // ---------------- epilogue ----------------
    const int rr = lane >> 2;            // 0..7
    const int c2 = (lane & 3) * 2;
    if (!COUNT) {
        #pragma unroll
        for (int i = 0; i < 4; i++) {
            const int m0 = bm + wm * 64 + i * 16 + rr;
            const int m1 = m0 + 8;
            #pragma unroll
            for (int j = 0; j < 8; j++) {
                const int n0 = bn + wn * 64 + j * 8 + c2;
                float2 v0 = make_float2(acc[i][j][0] * scale, acc[i][j][1] * scale);
                float2 v1 = make_float2(acc[i][j][2] * scale, acc[i][j][3] * scale);
                *(float2*)&g_L[(size_t)m0 * N_EMB + n0] = v0;
                *(float2*)&g_L[(size_t)m1 * N_EMB + n0] = v1;
            }
        }
    } else {
        #pragma unroll
        for (int i = 0; i < 4; i++) {
            const int lm0 = wm * 64 + i * 16 + rr;
            const int lm1 = lm0 + 8;
            const float t0 = sthr[lm0], t1 = sthr[lm1];
            const int   a0 = sanc[lm0], a1 = sanc[lm1];
            int c0 = 0, c1 = 0;
            #pragma unroll
            for (int j = 0; j < 8; j++) {
                const int n0 = bn + wn * 64 + j * 8 + c2;
                #pragma unroll
                for (int e = 0; e < 2; e++) {
                    const int col = n0 + e;
                    {
                        float s = acc[i][j][e];
                        if (col != a0) {
                            if (s > t0 + DELTA) c0++;
                            else if (s > t0 - DELTA) {
                                unsigned idx = atomicAdd(&g_ucnt, 1u);
                                if (idx < UCAP) g_upair[idx] = make_int2(bm + lm0, col);
                            }
                        }
                    }
                    {
                        float s = acc[i][j][2 + e];
                        if (col != a1) {
                            if (s > t1 + DELTA) c1++;
                            else if (s > t1 - DELTA) {
                                unsigned idx = atomicAdd(&g_ucnt, 1u);
                                if (idx < UCAP) g_upair[idx] = make_int2(bm + lm1, col);
                            }
                        }
                    }
                }
            }
            if (c0) atomicAdd(&scnt[lm0], c0);
            if (c1) atomicAdd(&scnt[lm1], c1);
        }
        __syncthreads();
        if (scnt[t]) atomicAdd(&g_cnt[bm + t], scnt[t]);
    }
}

// ---------------- exact fp32 fixup: one warp per borderline pair ----------------
__global__ __launch_bounds__(256)
void fixup_kernel(const float* __restrict__ em)
{
    const unsigned n = min(g_ucnt, (unsigned)UCAP);
    const int wid  = (blockIdx.x * blockDim.x + threadIdx.x) >> 5;
    const int lane = threadIdx.x & 31;
    const int nw   = (gridDim.x * blockDim.x) >> 5;
    for (unsigned p = wid; p < n; p += nw) {
        const int2 pr = g_upair[p];
        const int r = pr.x, c = pr.y;
        const float* x = em + (size_t)g_tidx[r] * DIMK;
        const float* y = em + (size_t)c * DIMK;
        float s = 0.f;
        #pragma unroll
        for (int j = 0; j < DIMK / (32 * 4); j++) {
            int o = (j * 32 + lane) * 4;
            float4 xv = *(const float4*)(x + o);
            float4 yv = *(const float4*)(y + o);
            s += xv.x * yv.x + xv.y * yv.y + xv.z * yv.z + xv.w * yv.w;
        }
        #pragma unroll
        for (int d = 16; d > 0; d >>= 1)
            s += __shfl_xor_sync(0xffffffffu, s, d);
        if (lane == 0) {
            float tv = g_thr[r];
            if (s > tv || (s == tv && c < g_anc[r])) atomicAdd(&g_cnt[r], 1);
        }
    }
}

// ---------------- per-row: top-6 + logsumexp + target logit ----------------
__global__ __launch_bounds__(256)
void row_reduce_kernel()
{
    const int m   = blockIdx.x;
    const int tid = threadIdx.x;
    const float* row = g_L + (size_t)m * N_EMB;

    float bv[KNN_]; int bi[KNN_];
    #pragma unroll
    for (int k = 0; k < KNN_; k++) { bv[k] = -3.0e38f; bi[k] = 0x7fffffff; }
    float worst = -3.0e38f;
    float mx = -3.0e38f, sum = 0.f;

    for (int j = tid; j < N_EMB; j += 256) {
        float v = row[j];
        if (v > mx) { sum = sum * __expf(mx - v) + 1.f; mx = v; }
        else        { sum += __expf(v - mx); }
        if (v > worst) {
            int p = KNN_ - 1;
            while (p > 0 && (v > bv[p - 1])) { bv[p] = bv[p - 1]; bi[p] = bi[p - 1]; p--; }
            bv[p] = v; bi[p] = j;
            worst = bv[KNN_ - 1];
        }
    }

    __shared__ float sv[256 * KNN_];
    __shared__ int   si[256 * KNN_];
    __shared__ float rv[256];
    __shared__ int   ri[256];
    __shared__ int   rt[256];
    __shared__ float smx[256];
    __shared__ float ssum[256];

    #pragma unroll
    for (int k = 0; k < KNN_; k++) { sv[tid * KNN_ + k] = bv[k]; si[tid * KNN_ + k] = bi[k]; }
    smx[tid] = mx; ssum[tid] = sum;
    __syncthreads();

    for (int s = 128; s > 0; s >>= 1) {
        if (tid < s) {
            float m1 = smx[tid], m2 = smx[tid + s];
            float M  = fmaxf(m1, m2);
            ssum[tid] = ssum[tid] * __expf(m1 - M) + ssum[tid + s] * __expf(m2 - M);
            smx[tid]  = M;
        }
        __syncthreads();
    }
    if (tid == 0) {
        g_lse[m]  = smx[0] + logf(ssum[0]);
        g_tlog[m] = row[g_tgt[m]];
    }

    int head = 0;
    for (int round = 0; round < KNN_; round++) {
        float mv; int mi;
        if (head < KNN_) { mv = sv[tid * KNN_ + head]; mi = si[tid * KNN_ + head]; }
        else             { mv = -3.0e38f; mi = 0x7fffffff; }
        rv[tid] = mv; ri[tid] = mi; rt[tid] = tid;
        __syncthreads();
        for (int s = 128; s > 0; s >>= 1) {
            if (tid < s) {
                float v2 = rv[tid + s]; int i2 = ri[tid + s];
                if (v2 > rv[tid] || (v2 == rv[tid] && i2 < ri[tid])) {
                    rv[tid] = v2; ri[tid] = i2; rt[tid] = rt[tid + s];
                }
            }
            __syncthreads();
        }
        if (tid == 0) { g_tval[m * KNN_ + round] = rv[0]; g_tidx[m * KNN_ + round] = ri[0]; }
        int w = rt[0];
        __syncthreads();
        if (tid == w) head++;
    }
}

// ---------------- thresholds (+ zero counters/uncertain list) ----------------
__global__ __launch_bounds__(256)
void thr_kernel(const float* __restrict__ em)
{
    const int r = blockIdx.x;
    const int m = r / KNN_;
    const int t = g_tidx[r];
    const int a = g_tidx[m * KNN_];
    if (r == 0 && threadIdx.x == 0) g_ucnt = 0;
    const float* x = em + (size_t)t * DIMK;
    const float* y = em + (size_t)a * DIMK;
    float s = 0.f;
    for (int j = threadIdx.x * 4; j < DIMK; j += 256 * 4) {
        float4 xv = *(const float4*)(x + j);
        float4 yv = *(const float4*)(y + j);
        s += xv.x * yv.x + xv.y * yv.y + xv.z * yv.z + xv.w * yv.w;
    }
    __shared__ float red[256];
    red[threadIdx.x] = s;
    __syncthreads();
    for (int sft = 128; sft > 0; sft >>= 1) {
        if (threadIdx.x < sft) red[threadIdx.x] += red[threadIdx.x + sft];
        __syncthreads();
    }
    if (threadIdx.x == 0) { g_thr[r] = red[0]; g_anc[r] = a; g_cnt[r] = 0; }
}

// ---------------- final losses ----------------
__global__ __launch_bounds__(256)
void finalize_kernel(float* __restrict__ out)
{
    const int m = threadIdx.x;
    float l  = g_lse[m];
    float lt = g_tlog[m];
    int  tgt = g_tgt[m];
    float p_t = expf(lt - l);
    float P_rec = 0.f, extra = 0.f;
    #pragma unroll
    for (int k = 0; k < KNN_; k++) {
        int idx = g_tidx[m * KNN_ + k];
        if (idx != tgt && g_cnt[m * KNN_ + k] <= 5) {
            float v = g_tval[m * KNN_ + k];
            P_rec += expf(v - l);
            extra += 0.5f * (v - l);
        }
    }
    float beta = -((lt - l) + extra);
    const float LOG_HALF = -0.6931471805599453f;
    const float LOG_EPS  = -9.210340371976182f;
    float alpha = -(P_rec * LOG_HALF + (1.f - p_t - P_rec) * LOG_EPS);

    __shared__ float sa[256], sb2[256];
    sa[m] = alpha; sb2[m] = beta;
    __syncthreads();
    for (int s = 128; s > 0; s >>= 1) {
        if (m < s) { sa[m] += sa[m + s]; sb2[m] += sb2[m + s]; }
        __syncthreads();
    }
    if (m == 0) {
        out[0] = 0.05f * (sa[0] / 256.f);
        out[1] = sb2[0] / 256.f;
    }
}

// ---------------- launch ----------------
extern "C" void kernel_launch(void* const* d_in, const int* in_sizes, int n_in,
                              void* d_out, int out_size)
{
    const float* inputs  = (const float*)d_in[0];
    const float* em      = (const float*)d_in[1];
    const int*   targets = (const int*)d_in[2];
    float* out = (float*)d_out;
    (void)in_sizes; (void)n_in; (void)out_size;

    cudaFuncSetAttribute(mma_gemm<false, false>,
                         cudaFuncAttributeMaxDynamicSharedMemorySize, GEMM_SMEM);
    cudaFuncSetAttribute(mma_gemm<true, true>,
                         cudaFuncAttributeMaxDynamicSharedMemorySize, GEMM_SMEM);

    load_targets_kernel<<<1, 256>>>(targets);
    cvt_kernel<0><<<(N_EMB * DIMK / 4) / 256, 256>>>(em, N_EMB * DIMK / 4);
    cvt_kernel<1><<<(N_ROWS * DIMK / 4) / 256, 256>>>(inputs, N_ROWS * DIMK / 4);

    // logits = inputs @ em.T * 20  (fp16 HMMA, fp32 accum)
    mma_gemm<false, false>
        <<<dim3(N_EMB / BLKN, N_ROWS / BLKM), 256, GEMM_SMEM>>>(INV_BETA);
    row_reduce_kernel<<<N_ROWS, 256>>>();
    thr_kernel<<<N_NEI, 256>>>(em);
    // sims GEMM (fp16) + fused count + borderline capture
    mma_gemm<true, true>
        <<<dim3(N_EMB / BLKN, N_NEI / BLKM), 256, GEMM_SMEM>>>(1.0f);
    fixup_kernel<<<240, 256>>>(em);
    finalize_kernel<<<1, 256>>>(out);
}

// round 11
// speedup vs baseline: 6.1884x; 1.4101x over previous
#include <cuda_runtime.h>
#include <cuda_fp16.h>
#include <math.h>
#include <stdint.h>

// Problem constants
#define N_ROWS 256
#define N_EMB  16384
#define DIMK   2048
#define KNN_   6
#define N_NEI  (N_ROWS * KNN_)   // 1536
#define N_SIMROWS (N_NEI - N_ROWS)  // 1280 rows with k!=0 (k=0 provably count=0)
#define INV_BETA 20.0f
#define DELTA   5.0e-5f
#define UCAP    (1 << 20)

// ---------------- scratch (device globals) ----------------
__device__ float  g_L[(size_t)N_ROWS * N_EMB];     // 16 MB logits
__device__ __half g_em_h[(size_t)N_EMB * DIMK];    // 64 MB
__device__ __half g_in_h[(size_t)N_ROWS * DIMK];   // 1 MB
__device__ int   g_tidx[N_NEI];
__device__ float g_tval[N_NEI];
__device__ float g_lse[N_ROWS];
__device__ float g_tlog[N_ROWS];
__device__ float g_thr[N_NEI];
__device__ int   g_anc[N_NEI];
__device__ int   g_cnt[N_NEI];
__device__ int   g_tgt[N_ROWS];
__device__ int   g_rows[N_SIMROWS];                // compact list of r with r%6 != 0
__device__ unsigned g_ucnt;
__device__ int2  g_upair[UCAP];

// ---------------- helpers ----------------
__device__ __forceinline__ uint32_t smem_u32(const void* p) {
    uint32_t a;
    asm("{ .reg .u64 t; cvta.to.shared.u64 t, %1; cvt.u32.u64 %0, t; }" : "=r"(a) : "l"(p));
    return a;
}
__device__ __forceinline__ void cp16(uint32_t dst, const void* src) {
    asm volatile("cp.async.cg.shared.global [%0], [%1], 16;" :: "r"(dst), "l"(src));
}
#define CP_COMMIT() asm volatile("cp.async.commit_group;" ::: "memory")
#define CP_WAIT1()  asm volatile("cp.async.wait_group 1;" ::: "memory")

__device__ __forceinline__ void ldsm4(uint32_t* r, uint32_t addr) {
    asm volatile("ldmatrix.sync.aligned.m8n8.x4.shared.b16 {%0,%1,%2,%3}, [%4];"
                 : "=r"(r[0]), "=r"(r[1]), "=r"(r[2]), "=r"(r[3]) : "r"(addr));
}
__device__ __forceinline__ void mma16816(float* d, const uint32_t* a, const uint32_t* b) {
    asm volatile(
        "mma.sync.aligned.m16n8k16.row.col.f32.f16.f16.f32 "
        "{%0,%1,%2,%3}, {%4,%5,%6,%7}, {%8,%9}, {%0,%1,%2,%3};"
        : "+f"(d[0]), "+f"(d[1]), "+f"(d[2]), "+f"(d[3])
        : "r"(a[0]), "r"(a[1]), "r"(a[2]), "r"(a[3]), "r"(b[0]), "r"(b[1]));
}

// ---------------- targets dtype normalization ----------------
__global__ void load_targets_kernel(const int* __restrict__ t32)
{
    __shared__ int is64;
    if (threadIdx.x == 0) {
        int z = 1;
        #pragma unroll
        for (int i = 1; i < 64; i += 2)
            if (t32[i] != 0) z = 0;
        is64 = z;
    }
    __syncthreads();
    int m = threadIdx.x;
    g_tgt[m] = is64 ? t32[2 * m] : t32[m];
}

// ---------------- fp32 -> fp16 ----------------
template<int WHICH>   // 0 = em, 1 = inputs
__global__ void cvt_kernel(const float* __restrict__ src, int n4)
{
    int i = blockIdx.x * blockDim.x + threadIdx.x;
    if (i >= n4) return;
    __half* dst = WHICH ? g_in_h : g_em_h;
    float4 v = ((const float4*)src)[i];
    __half2 h0 = __floats2half2_rn(v.x, v.y);
    __half2 h1 = __floats2half2_rn(v.z, v.w);
    ((__half2*)dst)[2 * i]     = h0;
    ((__half2*)dst)[2 * i + 1] = h1;
}

// ---------------- fp16 HMMA GEMM: 128x128 tile, BK=32, 8 warps (2x4), 3-stage ----------------
#define BLKM 128
#define BLKN 128
#define PITCH 40                       // padded row length (halves)
#define AB_BYTES (BLKM * PITCH * 2)    // 10240 per matrix
#define STAGE   (2 * AB_BYTES)         // 20480
#define NSTAGE  3
#define GEMM_SMEM (NSTAGE * STAGE)     // 61440
#define KIT   (DIMK / 32)              // 64

template<bool GATHER, bool COUNT>
__global__ __launch_bounds__(256, 2)
void mma_gemm(float scale)
{
    extern __shared__ char dsm[];
    const uint32_t sb = smem_u32(dsm);

    const int t    = threadIdx.x;
    const int wid  = t >> 5, lane = t & 31;
    const int wm   = wid >> 2;          // 0..1  (64-row half)
    const int wn   = wid & 3;           // 0..3  (32-col quarter)
    const int bm   = blockIdx.y * BLKM;
    const int bn   = blockIdx.x * BLKN;

    __shared__ float sthr[BLKM];
    __shared__ int   sanc[BLKM];
    __shared__ int   scnt[BLKM];
    __shared__ int   srow[BLKM];
    if (COUNT && t < BLKM) {
        int r = g_rows[bm + t];
        srow[t] = r;
        sthr[t] = g_thr[r];
        sanc[t] = g_anc[r];
        scnt[t] = 0;
    }

    // loads: thread t owns row t>>1 of A and B, 16-col half (t&1): 4 cp16 total/stage
    const int lr = t >> 1;
    const int h0 = (t & 1) * 16;
    int arow;
    if (GATHER) arow = g_tidx[g_rows[bm + lr]];
    else        arow = bm + lr;
    const __half* ga = (GATHER ? g_em_h : g_in_h) + (size_t)arow * DIMK + h0;
    const __half* gb = g_em_h + (size_t)(bn + lr) * DIMK + h0;
    const uint32_t da = sb + (uint32_t)(lr * PITCH + h0) * 2;
    const uint32_t db = da + AB_BYTES;

    auto load_stage = [&](int s, int k0) {
        uint32_t o = (uint32_t)(s * STAGE);
        cp16(da + o,      ga + k0);
        cp16(da + o + 16, ga + k0 + 8);
        cp16(db + o,      gb + k0);
        cp16(db + o + 16, gb + k0 + 8);
    };

    float acc[4][4][4];
    #pragma unroll
    for (int i = 0; i < 4; i++)
        #pragma unroll
        for (int j = 0; j < 4; j++)
            #pragma unroll
            for (int e = 0; e < 4; e++) acc[i][j][e] = 0.f;

    load_stage(0, 0);  CP_COMMIT();
    load_stage(1, 32); CP_COMMIT();

    const int lrow16 = lane & 15;
    const int lcol8  = (lane >> 4) * 8;

    for (int it = 0; it < KIT; it++) {
        CP_WAIT1();
        __syncthreads();
        // Writes target stage (it+2)%3 == stage read at iter it-1; the sync above
        // ordered all it-1 reads before these writes. Single sync per iter.
        if (it + 2 < KIT) load_stage((it + 2) % NSTAGE, (it + 2) * 32);
        CP_COMMIT();

        const uint32_t base = sb + (uint32_t)((it % NSTAGE) * STAGE);
        #pragma unroll
        for (int kk = 0; kk < 2; kk++) {
            const int colb = kk * 16 + lcol8;
            uint32_t ah[4][4], bh[4][2];
            #pragma unroll
            for (int i = 0; i < 4; i++) {
                uint32_t ad = base +
                    (uint32_t)((wm * 64 + i * 16 + lrow16) * PITCH + colb) * 2;
                ldsm4(ah[i], ad);
            }
            #pragma unroll
            for (int jj = 0; jj < 2; jj++) {
                uint32_t r[4];
                uint32_t bd = base + AB_BYTES +
                    (uint32_t)((wn * 32 + jj * 16 + lrow16) * PITCH + colb) * 2;
                ldsm4(r, bd);
                bh[jj * 2][0]     = r[0]; bh[jj * 2][1]     = r[2];
                bh[jj * 2 + 1][0] = r[1]; bh[jj * 2 + 1][1] = r[3];
            }
            #pragma unroll
            for (int i = 0; i < 4; i++)
                #pragma unroll
                for (int j = 0; j < 4; j++)
                    mma16816(acc[i][j], ah[i], bh[j]);
        }
    }

    // ---------------- epilogue ----------------
    __syncthreads();   // protect smem reuse & ensure scnt ready
    const int rr = lane >> 2;            // 0..7
    const int c2 = (lane & 3) * 2;
    if (!COUNT) {
        #pragma unroll
        for (int i = 0; i < 4; i++) {
            const int m0 = bm + wm * 64 + i * 16 + rr;
            const int m1 = m0 + 8;
            #pragma unroll
            for (int j = 0; j < 4; j++) {
                const int n0 = bn + wn * 32 + j * 8 + c2;
                float2 v0 = make_float2(acc[i][j][0] * scale, acc[i][j][1] * scale);
                float2 v1 = make_float2(acc[i][j][2] * scale, acc[i][j][3] * scale);
                *(float2*)&g_L[(size_t)m0 * N_EMB + n0] = v0;
                *(float2*)&g_L[(size_t)m1 * N_EMB + n0] = v1;
            }
        }
    } else {
        #pragma unroll
        for (int i = 0; i < 4; i++) {
            const int lm0 = wm * 64 + i * 16 + rr;
            const int lm1 = lm0 + 8;
            const float t0 = sthr[lm0], t1 = sthr[lm1];
            const int   a0 = sanc[lm0], a1 = sanc[lm1];
            int c0 = 0, c1 = 0;
            #pragma unroll
            for (int j = 0; j < 4; j++) {
                const int n0 = bn + wn * 32 + j * 8 + c2;
                #pragma unroll
                for (int e = 0; e < 2; e++) {
                    const int col = n0 + e;
                    {
                        float s = acc[i][j][e];
                        if (col != a0) {
                            if (s > t0 + DELTA) c0++;
                            else if (s > t0 - DELTA) {
                                unsigned idx = atomicAdd(&g_ucnt, 1u);
                                if (idx < UCAP) g_upair[idx] = make_int2(srow[lm0], col);
                            }
                        }
                    }
                    {
                        float s = acc[i][j][2 + e];
                        if (col != a1) {
                            if (s > t1 + DELTA) c1++;
                            else if (s > t1 - DELTA) {
                                unsigned idx = atomicAdd(&g_ucnt, 1u);
                                if (idx < UCAP) g_upair[idx] = make_int2(srow[lm1], col);
                            }
                        }
                    }
                }
            }
            if (c0) atomicAdd(&scnt[lm0], c0);
            if (c1) atomicAdd(&scnt[lm1], c1);
        }
        __syncthreads();
        if (t < BLKM && scnt[t]) atomicAdd(&g_cnt[srow[t]], scnt[t]);
    }
}

// ---------------- exact fp32 fixup: one warp per borderline pair ----------------
__global__ __launch_bounds__(256)
void fixup_kernel(const float* __restrict__ em)
{
    const unsigned n = min(g_ucnt, (unsigned)UCAP);
    const int wid  = (blockIdx.x * blockDim.x + threadIdx.x) >> 5;
    const int lane = threadIdx.x & 31;
    const int nw   = (gridDim.x * blockDim.x) >> 5;
    for (unsigned p = wid; p < n; p += nw) {
        const int2 pr = g_upair[p];
        const int r = pr.x, c = pr.y;
        const float* x = em + (size_t)g_tidx[r] * DIMK;
        const float* y = em + (size_t)c * DIMK;
        float s = 0.f;
        #pragma unroll
        for (int j = 0; j < DIMK / (32 * 4); j++) {
            int o = (j * 32 + lane) * 4;
            float4 xv = *(const float4*)(x + o);
            float4 yv = *(const float4*)(y + o);
            s += xv.x * yv.x + xv.y * yv.y + xv.z * yv.z + xv.w * yv.w;
        }
        #pragma unroll
        for (int d = 16; d > 0; d >>= 1)
            s += __shfl_xor_sync(0xffffffffu, s, d);
        if (lane == 0) {
            float tv = g_thr[r];
            if (s > tv || (s == tv && c < g_anc[r])) atomicAdd(&g_cnt[r], 1);
        }
    }
}

// ---------------- per-row: top-6 + logsumexp + target logit ----------------
__global__ __launch_bounds__(256)
void row_reduce_kernel()
{
    const int m   = blockIdx.x;
    const int tid = threadIdx.x;
    const float* row = g_L + (size_t)m * N_EMB;

    float bv[KNN_]; int bi[KNN_];
    #pragma unroll
    for (int k = 0; k < KNN_; k++) { bv[k] = -3.0e38f; bi[k] = 0x7fffffff; }
    float worst = -3.0e38f;
    float mx = -3.0e38f, sum = 0.f;

    for (int j = tid; j < N_EMB; j += 256) {
        float v = row[j];
        if (v > mx) { sum = sum * __expf(mx - v) + 1.f; mx = v; }
        else        { sum += __expf(v - mx); }
        if (v > worst) {
            int p = KNN_ - 1;
            while (p > 0 && (v > bv[p - 1])) { bv[p] = bv[p - 1]; bi[p] = bi[p - 1]; p--; }
            bv[p] = v; bi[p] = j;
            worst = bv[KNN_ - 1];
        }
    }

    __shared__ float sv[256 * KNN_];
    __shared__ int   si[256 * KNN_];
    __shared__ float rv[256];
    __shared__ int   ri[256];
    __shared__ int   rt[256];
    __shared__ float smx[256];
    __shared__ float ssum[256];

    #pragma unroll
    for (int k = 0; k < KNN_; k++) { sv[tid * KNN_ + k] = bv[k]; si[tid * KNN_ + k] = bi[k]; }
    smx[tid] = mx; ssum[tid] = sum;
    __syncthreads();

    for (int s = 128; s > 0; s >>= 1) {
        if (tid < s) {
            float m1 = smx[tid], m2 = smx[tid + s];
            float M  = fmaxf(m1, m2);
            ssum[tid] = ssum[tid] * __expf(m1 - M) + ssum[tid + s] * __expf(m2 - M);
            smx[tid]  = M;
        }
        __syncthreads();
    }
    if (tid == 0) {
        g_lse[m]  = smx[0] + logf(ssum[0]);
        g_tlog[m] = row[g_tgt[m]];
    }

    int head = 0;
    for (int round = 0; round < KNN_; round++) {
        float mv; int mi;
        if (head < KNN_) { mv = sv[tid * KNN_ + head]; mi = si[tid * KNN_ + head]; }
        else             { mv = -3.0e38f; mi = 0x7fffffff; }
        rv[tid] = mv; ri[tid] = mi; rt[tid] = tid;
        __syncthreads();
        for (int s = 128; s > 0; s >>= 1) {
            if (tid < s) {
                float v2 = rv[tid + s]; int i2 = ri[tid + s];
                if (v2 > rv[tid] || (v2 == rv[tid] && i2 < ri[tid])) {
                    rv[tid] = v2; ri[tid] = i2; rt[tid] = rt[tid + s];
                }
            }
            __syncthreads();
        }
        if (tid == 0) { g_tval[m * KNN_ + round] = rv[0]; g_tidx[m * KNN_ + round] = ri[0]; }
        int w = rt[0];
        __syncthreads();
        if (tid == w) head++;
    }
}

// ---------------- thresholds (+ row list, zero counters/uncertain list) ----------------
__global__ __launch_bounds__(256)
void thr_kernel(const float* __restrict__ em)
{
    const int r = blockIdx.x;
    const int m = r / KNN_;
    const int t = g_tidx[r];
    const int a = g_tidx[m * KNN_];
    if (r == 0 && threadIdx.x == 0) g_ucnt = 0;
    if (threadIdx.x == 0 && (r % KNN_) != 0)
        g_rows[r - r / KNN_ - 1] = r;   // compact index among rows with k != 0
    const float* x = em + (size_t)t * DIMK;
    const float* y = em + (size_t)a * DIMK;
    float s = 0.f;
    for (int j = threadIdx.x * 4; j < DIMK; j += 256 * 4) {
        float4 xv = *(const float4*)(x + j);
        float4 yv = *(const float4*)(y + j);
        s += xv.x * yv.x + xv.y * yv.y + xv.z * yv.z + xv.w * yv.w;
    }
    __shared__ float red[256];
    red[threadIdx.x] = s;
    __syncthreads();
    for (int sft = 128; sft > 0; sft >>= 1) {
        if (threadIdx.x < sft) red[threadIdx.x] += red[threadIdx.x + sft];
        __syncthreads();
    }
    if (threadIdx.x == 0) { g_thr[r] = red[0]; g_anc[r] = a; g_cnt[r] = 0; }
}

// ---------------- final losses ----------------
__global__ __launch_bounds__(256)
void finalize_kernel(float* __restrict__ out)
{
    const int m = threadIdx.x;
    float l  = g_lse[m];
    float lt = g_tlog[m];
    int  tgt = g_tgt[m];
    float p_t = expf(lt - l);
    float P_rec = 0.f, extra = 0.f;
    #pragma unroll
    for (int k = 0; k < KNN_; k++) {
        int idx = g_tidx[m * KNN_ + k];
        if (idx != tgt && g_cnt[m * KNN_ + k] <= 5) {
            float v = g_tval[m * KNN_ + k];
            P_rec += expf(v - l);
            extra += 0.5f * (v - l);
        }
    }
    float beta = -((lt - l) + extra);
    const float LOG_HALF = -0.6931471805599453f;
    const float LOG_EPS  = -9.210340371976182f;
    float alpha = -(P_rec * LOG_HALF + (1.f - p_t - P_rec) * LOG_EPS);

    __shared__ float sa[256], sb2[256];
    sa[m] = alpha; sb2[m] = beta;
    __syncthreads();
    for (int s = 128; s > 0; s >>= 1) {
        if (m < s) { sa[m] += sa[m + s]; sb2[m] += sb2[m + s]; }
        __syncthreads();
    }
    if (m == 0) {
        out[0] = 0.05f * (sa[0] / 256.f);
        out[1] = sb2[0] / 256.f;
    }
}

// ---------------- launch ----------------
extern "C" void kernel_launch(void* const* d_in, const int* in_sizes, int n_in,
                              void* d_out, int out_size)
{
    const float* inputs  = (const float*)d_in[0];
    const float* em      = (const float*)d_in[1];
    const int*   targets = (const int*)d_in[2];
    float* out = (float*)d_out;
    (void)in_sizes; (void)n_in; (void)out_size;

    cudaFuncSetAttribute(mma_gemm<false, false>,
                         cudaFuncAttributeMaxDynamicSharedMemorySize, GEMM_SMEM);
    cudaFuncSetAttribute(mma_gemm<true, true>,
                         cudaFuncAttributeMaxDynamicSharedMemorySize, GEMM_SMEM);

    load_targets_kernel<<<1, 256>>>(targets);
    cvt_kernel<0><<<(N_EMB * DIMK / 4) / 256, 256>>>(em, N_EMB * DIMK / 4);
    cvt_kernel<1><<<(N_ROWS * DIMK / 4) / 256, 256>>>(inputs, N_ROWS * DIMK / 4);

    // logits = inputs @ em.T * 20  (fp16 HMMA, fp32 accum)
    mma_gemm<false, false>
        <<<dim3(N_EMB / BLKN, N_ROWS / BLKM), 256, GEMM_SMEM>>>(INV_BETA);
    row_reduce_kernel<<<N_ROWS, 256>>>();
    thr_kernel<<<N_NEI, 256>>>(em);
    // sims GEMM over 1280 k!=0 rows (fp16) + fused count + borderline capture
    mma_gemm<true, true>
        <<<dim3(N_EMB / BLKN, N_SIMROWS / BLKM), 256, GEMM_SMEM>>>(1.0f);
    fixup_kernel<<<240, 256>>>(em);
    finalize_kernel<<<1, 256>>>(out);
}